// round 5
// baseline (speedup 1.0000x reference)
#include <cuda_runtime.h>

#define NL 7
#define BATCH 524288
#define TPB 256
// per-block position staging: NL * TPB * 3 floats = 5376 floats = 21 KB
#define POS_PER_LINK (TPB * 3)

__global__ __launch_bounds__(TPB)
void fk_quat_kernel(const float* __restrict__ q,
                    const float* __restrict__ rot_fixed,
                    const float* __restrict__ trans_fixed,
                    float* __restrict__ out)
{
    __shared__ float4 sQF[NL];            // fixed rotation as quaternion (x,y,z,w)
    __shared__ float  sTF[NL * 3];
    __shared__ __align__(16) float sPos[NL * POS_PER_LINK];  // 21 KB staging

    const int tid = threadIdx.x;
    if (tid < NL) {
        const float* R = rot_fixed + tid * 9;
        float r00 = R[0], r01 = R[1], r02 = R[2];
        float r10 = R[3], r11 = R[4], r12 = R[5];
        float r20 = R[6], r21 = R[7], r22 = R[8];
        const float eps = 1e-9f;
        float qw = 0.5f * sqrtf(fmaxf(1.f + r00 + r11 + r22, eps));
        float qx = 0.5f * sqrtf(fmaxf(1.f + r00 - r11 - r22, eps));
        float qy = 0.5f * sqrtf(fmaxf(1.f - r00 + r11 - r22, eps));
        float qz = 0.5f * sqrtf(fmaxf(1.f - r00 - r11 + r22, eps));
        qx = copysignf(qx, r21 - r12);
        qy = copysignf(qy, r02 - r20);
        qz = copysignf(qz, r10 - r01);
        sQF[tid] = make_float4(qx, qy, qz, qw);
    }
    if (tid < NL * 3) sTF[tid] = trans_fixed[tid];
    __syncthreads();

    const int b = blockIdx.x * TPB + tid;   // BATCH % TPB == 0, no guard needed

    float qv[NL];
    #pragma unroll
    for (int i = 0; i < NL; i++) qv[i] = __ldg(&q[b * NL + i]);

    // Parent world pose: identity quaternion + zero translation
    float px = 0.f, py = 0.f, pz = 0.f, pw = 1.f;
    float tx = 0.f, ty = 0.f, tz = 0.f;

    float4* qu_out = (float4*)(out + (size_t)NL * BATCH * 3);  // [NL, BATCH, 4]

    #pragma unroll
    for (int l = 0; l < NL; l++) {
        // ---- translation update: t += Rp @ tf  (rotate tf by parent quat) ----
        {
            float vx = sTF[l * 3 + 0], vy = sTF[l * 3 + 1], vz = sTF[l * 3 + 2];
            float c1x = fmaf(py, vz, -pz * vy);
            float c1y = fmaf(pz, vx, -px * vz);
            float c1z = fmaf(px, vy, -py * vx);
            float c2x = fmaf(pw, c1x, fmaf(py, c1z, -pz * c1y));
            float c2y = fmaf(pw, c1y, fmaf(pz, c1x, -px * c1z));
            float c2z = fmaf(pw, c1z, fmaf(px, c1y, -py * c1x));
            tx = fmaf(2.f, c2x, tx + vx);
            ty = fmaf(2.f, c2y, ty + vy);
            tz = fmaf(2.f, c2z, tz + vz);
        }

        // ---- orientation update: p = p (x) qf[l] (x) q_axis ----
        {
            float4 f = sQF[l];
            float mw = fmaf(pw, f.w, -fmaf(px, f.x, fmaf(py, f.y, pz * f.z)));
            float mx = fmaf(pw, f.x, fmaf(px, f.w, fmaf(py, f.z, -pz * f.y)));
            float my = fmaf(pw, f.y, fmaf(-px, f.z, fmaf(py, f.w, pz * f.x)));
            float mz = fmaf(pw, f.z, fmaf(px, f.y, fmaf(-py, f.x, pz * f.w)));

            float s, c;
            __sincosf(0.5f * qv[l], &s, &c);

            if ((l & 1) == 0) {
                // axis z: qa = (0,0,s,c)
                pw = fmaf(mw, c, -mz * s);
                px = fmaf(mx, c,  my * s);
                py = fmaf(my, c, -mx * s);
                pz = fmaf(mw, s,  mz * c);
            } else {
                // axis y: qa = (0,s,0,c)
                pw = fmaf(mw, c, -my * s);
                px = fmaf(mx, c, -mz * s);
                py = fmaf(mw, s,  my * c);
                pz = fmaf(mz, c,  mx * s);
            }
        }

        // ---- stage position in shared (stride-3, bank-conflict-free) ----
        sPos[l * POS_PER_LINK + tid * 3 + 0] = tx;
        sPos[l * POS_PER_LINK + tid * 3 + 1] = ty;
        sPos[l * POS_PER_LINK + tid * 3 + 2] = tz;

        // ---- canonical quaternion (w >= 0), coalesced float4 store ----
        float sgn = (pw < 0.f) ? -1.f : 1.f;
        qu_out[(size_t)l * BATCH + b] =
            make_float4(sgn * px, sgn * py, sgn * pz, sgn * pw);
    }

    __syncthreads();

    // ---- flush positions: per link, 768 contiguous floats = 192 float4 ----
    const float4* sp4 = (const float4*)sPos;
    #pragma unroll
    for (int l = 0; l < NL; l++) {
        if (tid < POS_PER_LINK / 4) {   // 192 of 256 threads
            float4* gp4 = (float4*)(out + (size_t)l * BATCH * 3
                                        + (size_t)blockIdx.x * POS_PER_LINK);
            gp4[tid] = sp4[l * (POS_PER_LINK / 4) + tid];
        }
    }
}

extern "C" void kernel_launch(void* const* d_in, const int* in_sizes, int n_in,
                              void* d_out, int out_size) {
    const float* q           = (const float*)d_in[0];
    const float* rot_fixed   = (const float*)d_in[1];
    const float* trans_fixed = (const float*)d_in[2];
    float* out = (float*)d_out;

    const int blocks = BATCH / TPB;
    fk_quat_kernel<<<blocks, TPB>>>(q, rot_fixed, trans_fixed, out);
}